// round 3
// baseline (speedup 1.0000x reference)
#include <cuda_runtime.h>

#define N_NODES 100000
#define N_EDGES 3200000

// Per-node partial sums for hidden units 0,1 (interleaved for v2 atomics).
// Zero-initialized at module load; node_kernel re-zeroes after consuming,
// so every replay of the captured graph sees zeros on entry.
static __device__ float g_acc[2 * N_NODES];

// One-shot: each thread handles 2 consecutive edges (N_EDGES % 2 == 0).
// Contribution of edge e: edge_attr[e] . W1[3:19, j], j=0,1 -> node col[e].
__global__ void __launch_bounds__(256) edge_kernel(
        const float4* __restrict__ ea,
        const int2*   __restrict__ col2,
        const float*  __restrict__ W1) {
    float w0[16], w1[16];
#pragma unroll
    for (int k = 0; k < 16; ++k) {
        w0[k] = __ldg(&W1[(3 + k) * 2 + 0]);
        w1[k] = __ldg(&W1[(3 + k) * 2 + 1]);
    }
    const int q = blockIdx.x * blockDim.x + threadIdx.x;  // edge pair id
    if (q >= N_EDGES / 2) return;

    int2 nn = __ldg(col2 + q);
    const float4* base = ea + (size_t)q * 8;

    float4 r[8];
#pragma unroll
    for (int i = 0; i < 8; ++i) r[i] = __ldg(base + i);

#pragma unroll
    for (int e = 0; e < 2; ++e) {
        const float4 a = r[4 * e + 0], b = r[4 * e + 1];
        const float4 c = r[4 * e + 2], d = r[4 * e + 3];
        float d0 = a.x * w0[0]  + a.y * w0[1]  + a.z * w0[2]  + a.w * w0[3]
                 + b.x * w0[4]  + b.y * w0[5]  + b.z * w0[6]  + b.w * w0[7]
                 + c.x * w0[8]  + c.y * w0[9]  + c.z * w0[10] + c.w * w0[11]
                 + d.x * w0[12] + d.y * w0[13] + d.z * w0[14] + d.w * w0[15];
        float d1 = a.x * w1[0]  + a.y * w1[1]  + a.z * w1[2]  + a.w * w1[3]
                 + b.x * w1[4]  + b.y * w1[5]  + b.z * w1[6]  + b.w * w1[7]
                 + c.x * w1[8]  + c.y * w1[9]  + c.z * w1[10] + c.w * w1[11]
                 + d.x * w1[12] + d.y * w1[13] + d.z * w1[14] + d.w * w1[15];
        int n = (e == 0) ? nn.x : nn.y;
        float* p = g_acc + 2 * n;  // 8B-aligned
        asm volatile("red.global.add.v2.f32 [%0], {%1, %2};"
                     :: "l"(p), "f"(d0), "f"(d1) : "memory");
    }
}

__global__ void node_kernel(const float* __restrict__ x,
                            const float* __restrict__ W1,
                            const float* __restrict__ b1,
                            const float* __restrict__ W2,
                            const float* __restrict__ b2,
                            float* __restrict__ out) {
    int n = blockIdx.x * blockDim.x + threadIdx.x;
    if (n >= N_NODES) return;

    float vi = x[3 * n + 0];
    float s1 = x[3 * n + 1];
    float s2 = x[3 * n + 2];

    // Consume and reset accumulator (keeps g_acc zeroed for the next replay).
    float2* accp = (float2*)(g_acc + 2 * n);
    float2 acc = *accp;
    *accp = make_float2(0.0f, 0.0f);

    // hidden units (only needed for output column 2)
    float h0 = acc.x + __ldg(&b1[0]);
    h0 = fmaf(vi, __ldg(&W1[0]), fmaf(s1, __ldg(&W1[2]), fmaf(s2, __ldg(&W1[4]), h0)));
    float h1 = acc.y + __ldg(&b1[1]);
    h1 = fmaf(vi, __ldg(&W1[1]), fmaf(s1, __ldg(&W1[3]), fmaf(s2, __ldg(&W1[5]), h1)));
    h0 = fmaxf(h0, 0.0f);
    h1 = fmaxf(h1, 0.0f);
    // W2 is [2,3] row-major; output column 2 uses W2[2], W2[5]
    float o2 = fmaf(h0, __ldg(&W2[2]), fmaf(h1, __ldg(&W2[5]), __ldg(&b2[2])));

    // closed-form overrides (depend only on x)
    float n1 = (powf(0.7660379f, s2 / 0.3038425f + s1)
                + powf(0.12117091f, s1) / -0.7256157f)
               * powf(1.2125463f, vi) + 0.12262904f;

    float t = s2 + (s1 + -3.283101f - vi / 0.79082423f) * 0.31992579f;
    float n1n2 = 0.7872602f - sqrtf(logf(powf(0.1562228f, t) + 1.4462701f));

    out[3 * n + 0] = n1 + vi;
    out[3 * n + 1] = (n1n2 - n1) + s1;
    out[3 * n + 2] = o2 + s2;
}

extern "C" void kernel_launch(void* const* d_in, const int* in_sizes, int n_in,
                              void* d_out, int out_size) {
    // metadata order: x, edge_attr, u, W1, b1, W2, b2, edge_index, batch
    const float*  x   = (const float*)d_in[0];
    const float4* ea  = (const float4*)d_in[1];
    const float*  W1  = (const float*)d_in[3];
    const float*  b1  = (const float*)d_in[4];
    const float*  W2  = (const float*)d_in[5];
    const float*  b2  = (const float*)d_in[6];
    const int*    ei  = (const int*)d_in[7];          // int32 (JAX x64 off)
    const int2*   col2 = (const int2*)(ei + N_EDGES); // edge_index[1], paired
    float* out = (float*)d_out;

    edge_kernel<<<(N_EDGES / 2 + 255) / 256, 256>>>(ea, col2, W1);
    node_kernel<<<(N_NODES + 255) / 256, 256>>>(x, W1, b1, W2, b2, out);
}

// round 5
// speedup vs baseline: 1.6749x; 1.6749x over previous
#include <cuda_runtime.h>

#define N_NODES 100000
#define N_EDGES 3200000

// Per-node partial sums for hidden units 0,1 (interleaved for v2 atomics).
// Zero-initialized at module load; node_kernel consumes AND resets, so every
// replay of the captured graph sees zeros on entry.
static __device__ float g_acc[2 * N_NODES];

// Warp-cooperative, fully coalesced edge aggregation.
// Warp w owns edges [32w, 32w+32). Lane l loads float4 flat = 128w + l + 32i
// (coalesced), which is chunk c=l&3 of edge 32w + (l>>2) + 8i. Butterfly
// shuffles (xor 1,2) sum the 4 chunk-dots; lane 4j issues one red.v2.
__global__ void __launch_bounds__(256) edge_kernel(
        const float4* __restrict__ ea,
        const int*    __restrict__ col,
        const float*  __restrict__ W1) {
    const int warp_id = (blockIdx.x * blockDim.x + threadIdx.x) >> 5;
    const int lane = threadIdx.x & 31;
    if (warp_id >= N_EDGES / 32) return;
    const int eBase = warp_id * 32;
    const int c = lane & 3;

    // W1 is [19,2] row-major; edge-feature rows are 3..18. Chunk c -> rows 3+4c..6+4c.
    float w0[4], w1[4];
#pragma unroll
    for (int k = 0; k < 4; ++k) {
        w0[k] = __ldg(&W1[(3 + 4 * c + k) * 2 + 0]);
        w1[k] = __ldg(&W1[(3 + 4 * c + k) * 2 + 1]);
    }

    const int myCol = __ldg(col + eBase + lane);       // coalesced
    const float4* base = ea + (size_t)eBase * 4;

#pragma unroll
    for (int i = 0; i < 4; ++i) {
        float4 v = __ldg(base + lane + 32 * i);        // coalesced: 4 lines/LDG
        float d0 = fmaf(v.x, w0[0], fmaf(v.y, w0[1], fmaf(v.z, w0[2], v.w * w0[3])));
        float d1 = fmaf(v.x, w1[0], fmaf(v.y, w1[1], fmaf(v.z, w1[2], v.w * w1[3])));
        d0 += __shfl_xor_sync(0xffffffffu, d0, 1);
        d0 += __shfl_xor_sync(0xffffffffu, d0, 2);
        d1 += __shfl_xor_sync(0xffffffffu, d1, 1);
        d1 += __shfl_xor_sync(0xffffffffu, d1, 2);
        // lane 4j now holds the full dot of edge eBase + j + 8i
        int n = __shfl_sync(0xffffffffu, myCol, (lane >> 2) + 8 * i);
        if (c == 0) {
            float* p = g_acc + 2 * n;  // 8B-aligned
            asm volatile("red.global.add.v2.f32 [%0], {%1, %2};"
                         :: "l"(p), "f"(d0), "f"(d1) : "memory");
        }
    }
}

__global__ void node_kernel(const float* __restrict__ x,
                            const float* __restrict__ W1,
                            const float* __restrict__ b1,
                            const float* __restrict__ W2,
                            const float* __restrict__ b2,
                            float* __restrict__ out) {
    int n = blockIdx.x * blockDim.x + threadIdx.x;
    if (n >= N_NODES) return;

    float vi = x[3 * n + 0];
    float s1 = x[3 * n + 1];
    float s2 = x[3 * n + 2];

    // Consume and reset accumulator (keeps g_acc zeroed for the next replay).
    float2* accp = (float2*)(g_acc + 2 * n);
    float2 acc = *accp;
    *accp = make_float2(0.0f, 0.0f);

    // hidden units (only needed for output column 2)
    float h0 = acc.x + __ldg(&b1[0]);
    h0 = fmaf(vi, __ldg(&W1[0]), fmaf(s1, __ldg(&W1[2]), fmaf(s2, __ldg(&W1[4]), h0)));
    float h1 = acc.y + __ldg(&b1[1]);
    h1 = fmaf(vi, __ldg(&W1[1]), fmaf(s1, __ldg(&W1[3]), fmaf(s2, __ldg(&W1[5]), h1)));
    h0 = fmaxf(h0, 0.0f);
    h1 = fmaxf(h1, 0.0f);
    // W2 is [2,3] row-major; output column 2 uses W2[2], W2[5]
    float o2 = fmaf(h0, __ldg(&W2[2]), fmaf(h1, __ldg(&W2[5]), __ldg(&b2[2])));

    // closed-form overrides (depend only on x)
    float n1 = (powf(0.7660379f, s2 / 0.3038425f + s1)
                + powf(0.12117091f, s1) / -0.7256157f)
               * powf(1.2125463f, vi) + 0.12262904f;

    float t = s2 + (s1 + -3.283101f - vi / 0.79082423f) * 0.31992579f;
    float n1n2 = 0.7872602f - sqrtf(logf(powf(0.1562228f, t) + 1.4462701f));

    out[3 * n + 0] = n1 + vi;
    out[3 * n + 1] = (n1n2 - n1) + s1;
    out[3 * n + 2] = o2 + s2;
}

extern "C" void kernel_launch(void* const* d_in, const int* in_sizes, int n_in,
                              void* d_out, int out_size) {
    // metadata order: x, edge_attr, u, W1, b1, W2, b2, edge_index, batch
    const float*  x   = (const float*)d_in[0];
    const float4* ea  = (const float4*)d_in[1];
    const float*  W1  = (const float*)d_in[3];
    const float*  b1  = (const float*)d_in[4];
    const float*  W2  = (const float*)d_in[5];
    const float*  b2  = (const float*)d_in[6];
    const int*    ei  = (const int*)d_in[7];   // int32 (JAX x64 off)
    const int*    col = ei + N_EDGES;          // edge_index[1]
    float* out = (float*)d_out;

    // 100000 warps, 8 warps/block -> 12500 blocks, no tail.
    edge_kernel<<<N_EDGES / 32 / 8, 256>>>(ea, col, W1);
    node_kernel<<<(N_NODES + 255) / 256, 256>>>(x, W1, b1, W2, b2, out);
}